// round 11
// baseline (speedup 1.0000x reference)
#include <cuda_runtime.h>
#include <cuda_fp16.h>
#include <cstdint>
#include <cstddef>

using half_t = __half;

#define SEQ  8192
#define DIN  1024
#define DOUT 1024

// ---------------- device scratch (static: allowed) ----------------
__device__ half_t g_xh [SEQ * DIN];
__device__ half_t g_Wqh[DOUT * DIN];
__device__ half_t g_Wkh[DOUT * DIN];
__device__ half_t g_Wvh[DOUT * DIN];
__device__ half_t g_Qh [SEQ * DOUT];
__device__ half_t g_Kh [SEQ * DOUT];
__device__ half_t g_Vth[(size_t)DOUT * SEQ];   // V transposed [DOUT][SEQ]
__device__ half_t g_Ph [(size_t)SEQ * SEQ];    // unnormalized exp(scores), fp16
__device__ float  g_InvRS[SEQ];                // 1 / rowsum(exp)

// ---------------- helpers ----------------
__device__ __forceinline__ uint32_t smem_u32(const void* p) {
    uint32_t a;
    asm("{ .reg .u64 t; cvta.to.shared.u64 t, %1; cvt.u32.u64 %0, t; }" : "=r"(a) : "l"(p));
    return a;
}
__device__ __forceinline__ void cp16(uint32_t dst, const void* src) {
    asm volatile("cp.async.cg.shared.global [%0], [%1], 16;" :: "r"(dst), "l"(src));
}
#define CP_COMMIT() asm volatile("cp.async.commit_group;" ::: "memory")
#define CP_WAIT1()  asm volatile("cp.async.wait_group 1;" ::: "memory")

__device__ __forceinline__ void ldm4(uint32_t* r, uint32_t addr) {
    asm volatile("ldmatrix.sync.aligned.m8n8.x4.shared.b16 {%0,%1,%2,%3}, [%4];"
                 : "=r"(r[0]), "=r"(r[1]), "=r"(r[2]), "=r"(r[3]) : "r"(addr));
}
__device__ __forceinline__ void mma16816(float* d, const uint32_t* a, const uint32_t* b) {
    asm volatile(
        "mma.sync.aligned.m16n8k16.row.col.f32.f16.f16.f32 "
        "{%0,%1,%2,%3}, {%4,%5,%6,%7}, {%8,%9}, {%0,%1,%2,%3};"
        : "+f"(d[0]), "+f"(d[1]), "+f"(d[2]), "+f"(d[3])
        : "r"(a[0]), "r"(a[1]), "r"(a[2]), "r"(a[3]), "r"(b[0]), "r"(b[1]));
}

// ---------------- conversion ----------------
__global__ void convert_hi_kernel(const float* __restrict__ src, half_t* __restrict__ hi, int n) {
    int i = blockIdx.x * blockDim.x + threadIdx.x;
    if (i < n) hi[i] = __float2half_rn(src[i]);
}

// ---------------- GEMM: C[128x256 tile] = alpha * A[MxK] * B[NxK]^T (plain fp16) ----------------
// 512 threads, 16 warps, warp tile 64x32, 2 CTAs/SM.
#define OUT_HI    0
#define OUT_HI_T  1
#define OUT_EXP   2
#define OUT_DIV   3

#define KT      32              // K elements per stage
#define STRIDE  40              // smem row stride in halves (80 B, conflict-free)
#define ROW_B   (STRIDE * 2)    // 80 bytes
#define OFF_B   (128 * ROW_B)   // A tile: 128 rows
#define STAGE_B (OFF_B + 256 * ROW_B)   // + B tile: 256 rows = 30720
#define STAGES  3
#define GEMM_SMEM (STAGES * STAGE_B)    // 92160 -> 2 CTAs/SM

template <int MODE>
__global__ __launch_bounds__(512, 2)
void gemm_nt_kernel(const half_t* __restrict__ Ah, const half_t* __restrict__ Bh,
                    float* __restrict__ outF, half_t* __restrict__ outH,
                    const float* __restrict__ invrs,
                    int K, int ldc, float alpha) {
    extern __shared__ half_t sm[];
    const uint32_t sbase = smem_u32(sm);
    const int tid  = threadIdx.x;
    const int lane = tid & 31;
    const int wid  = tid >> 5;
    const int m0 = blockIdx.y * 128;
    const int n0 = blockIdx.x * 256;
    const int wm = (wid & 1) * 64;         // warp M offset (2 warps in M)
    const int wn = (wid >> 1) * 32;        // warp N offset (8 warps in N)

    // --- cp.async addressing: 384 rows x 4 chunks = 1536 units, 3 per thread ---
    const half_t* srcp[3];
    uint32_t      soff[3];
#pragma unroll
    for (int i = 0; i < 3; i++) {
        int c = tid + i * 512;
        int row = c >> 2;
        int j = c & 3;
        if (row < 128) {
            srcp[i] = Ah + (size_t)(m0 + row) * K + j * 8;
            soff[i] = (uint32_t)(row * ROW_B + j * 16);
        } else {
            srcp[i] = Bh + (size_t)(n0 + row - 128) * K + j * 8;
            soff[i] = (uint32_t)(OFF_B + (row - 128) * ROW_B + j * 16);
        }
    }
    auto load_stage = [&](int s, int kt) {
        uint32_t dstb = sbase + s * STAGE_B;
        const int ko = kt * KT;
#pragma unroll
        for (int i = 0; i < 3; i++)
            cp16(dstb + soff[i], srcp[i] + ko);
    };

    float acc[4][4][4];
#pragma unroll
    for (int mt = 0; mt < 4; mt++)
#pragma unroll
        for (int nt = 0; nt < 4; nt++)
#pragma unroll
            for (int e = 0; e < 4; e++) acc[mt][nt][e] = 0.0f;

    // ldmatrix address components
    const int arow    = wm + (lane & 15);
    const int acolsel = ((lane >> 4) & 1) * 8;
    const int brow    = wn + ((lane >> 4) & 1) * 8 + (lane & 7);
    const int bcolsel = ((lane >> 3) & 1) * 8;

    const int nkt = K / KT;
    // prologue: 2 stages in flight
    load_stage(0, 0); CP_COMMIT();
    load_stage(1, 1); CP_COMMIT();

    int s = 0;
#pragma unroll 1
    for (int kt = 0; kt < nkt; kt++) {
        CP_WAIT1();
        __syncthreads();
        int ws = s + 2; if (ws >= 3) ws -= 3;   // slot (kt+2)%3 == (kt-1)%3, reads done
        if (kt + 2 < nkt) load_stage(ws, kt + 2);
        CP_COMMIT();

        const uint32_t stb = sbase + s * STAGE_B;
#pragma unroll
        for (int kk = 0; kk < 2; kk++) {
            const int kc = kk * 16;
            uint32_t a_h[4][4], b_h[4][2];
#pragma unroll
            for (int mt = 0; mt < 4; mt++) {
                uint32_t off = (uint32_t)(((arow + mt * 16) * STRIDE + kc + acolsel) * 2);
                ldm4(a_h[mt], stb + off);
            }
#pragma unroll
            for (int pt = 0; pt < 2; pt++) {
                uint32_t off = (uint32_t)((((brow + pt * 16) + 128) * STRIDE + kc + bcolsel) * 2);
                uint32_t r[4];
                ldm4(r, stb + off);
                b_h[2 * pt][0] = r[0]; b_h[2 * pt][1] = r[1];
                b_h[2 * pt + 1][0] = r[2]; b_h[2 * pt + 1][1] = r[3];
            }
#pragma unroll
            for (int mt = 0; mt < 4; mt++)
#pragma unroll
                for (int nt = 0; nt < 4; nt++)
                    mma16816(acc[mt][nt], a_h[mt], b_h[nt]);
        }
        s = (s == 2) ? 0 : s + 1;
    }

    // ---------------- epilogue (register-direct) ----------------
    const int rr = lane >> 2;
    const int cc = (lane & 3) * 2;
#pragma unroll
    for (int mt = 0; mt < 4; mt++) {
        int gm = m0 + wm + mt * 16 + rr;
        float inv0 = 0.f, inv1 = 0.f;
        if (MODE == OUT_DIV) { inv0 = invrs[gm]; inv1 = invrs[gm + 8]; }
#pragma unroll
        for (int nt = 0; nt < 4; nt++) {
            int gn = n0 + wn + nt * 8 + cc;
#pragma unroll
            for (int h = 0; h < 2; h++) {
                float v0 = acc[mt][nt][2 * h + 0] * alpha;
                float v1 = acc[mt][nt][2 * h + 1] * alpha;
                int m = gm + h * 8;
                if (MODE == OUT_HI) {
                    *(__half2*)(outH + (size_t)m * ldc + gn) =
                        __halves2half2(__float2half_rn(v0), __float2half_rn(v1));
                } else if (MODE == OUT_HI_T) {
                    outH[(size_t)gn * ldc + m]       = __float2half_rn(v0);
                    outH[(size_t)(gn + 1) * ldc + m] = __float2half_rn(v1);
                } else if (MODE == OUT_EXP) {
                    float e0 = __expf(v0);
                    float e1 = __expf(v1);
                    *(__half2*)(outH + (size_t)m * ldc + gn) =
                        __halves2half2(__float2half_rn(e0), __float2half_rn(e1));
                } else {  // OUT_DIV
                    float inv = (h == 0) ? inv0 : inv1;
                    float2 v; v.x = v0 * inv; v.y = v1 * inv;
                    *(float2*)(outF + (size_t)m * ldc + gn) = v;
                }
            }
        }
    }
}

// ---------------- per-row inverse sum of P~ (deterministic) ----------------
__global__ __launch_bounds__(256)
void rowinv_kernel(const half_t* __restrict__ Ph, float* __restrict__ inv) {
    __shared__ float red[8];
    const int row = blockIdx.x;
    const int tid = threadIdx.x;
    const __half2* p = (const __half2*)(Ph + (size_t)row * SEQ);

    float sum = 0.0f;
#pragma unroll 4
    for (int i = tid; i < SEQ / 2; i += 256) {
        float2 f = __half22float2(p[i]);
        sum += f.x + f.y;
    }
#pragma unroll
    for (int o = 16; o; o >>= 1) sum += __shfl_xor_sync(0xFFFFFFFFu, sum, o);
    if ((tid & 31) == 0) red[tid >> 5] = sum;
    __syncthreads();
    if (tid == 0) {
        float t = 0.0f;
#pragma unroll
        for (int j = 0; j < 8; j++) t += red[j];
        inv[row] = 1.0f / t;
    }
}

// ---------------- host ----------------
extern "C" void kernel_launch(void* const* d_in, const int* in_sizes, int n_in,
                              void* d_out, int out_size) {
    const float* x  = (const float*)d_in[0];
    const float* Wq = (const float*)d_in[1];
    const float* Wk = (const float*)d_in[2];
    const float* Wv = (const float*)d_in[3];
    float* out = (float*)d_out;

    half_t *xh, *wqh, *wkh, *wvh, *qh, *kh, *vth, *pph;
    float* invrs;
    cudaGetSymbolAddress((void**)&xh,    g_xh);
    cudaGetSymbolAddress((void**)&wqh,   g_Wqh);
    cudaGetSymbolAddress((void**)&wkh,   g_Wkh);
    cudaGetSymbolAddress((void**)&wvh,   g_Wvh);
    cudaGetSymbolAddress((void**)&qh,    g_Qh);
    cudaGetSymbolAddress((void**)&kh,    g_Kh);
    cudaGetSymbolAddress((void**)&vth,   g_Vth);
    cudaGetSymbolAddress((void**)&pph,   g_Ph);
    cudaGetSymbolAddress((void**)&invrs, g_InvRS);

    cudaFuncSetAttribute((const void*)gemm_nt_kernel<OUT_HI>,
                         cudaFuncAttributeMaxDynamicSharedMemorySize, GEMM_SMEM);
    cudaFuncSetAttribute((const void*)gemm_nt_kernel<OUT_HI_T>,
                         cudaFuncAttributeMaxDynamicSharedMemorySize, GEMM_SMEM);
    cudaFuncSetAttribute((const void*)gemm_nt_kernel<OUT_EXP>,
                         cudaFuncAttributeMaxDynamicSharedMemorySize, GEMM_SMEM);
    cudaFuncSetAttribute((const void*)gemm_nt_kernel<OUT_DIV>,
                         cudaFuncAttributeMaxDynamicSharedMemorySize, GEMM_SMEM);

    // 1) convert all fp32 inputs to fp16 (round-to-nearest)
    convert_hi_kernel<<<(SEQ * DIN + 255) / 256, 256>>>(x,  xh,  SEQ * DIN);
    convert_hi_kernel<<<(DOUT * DIN + 255) / 256, 256>>>(Wq, wqh, DOUT * DIN);
    convert_hi_kernel<<<(DOUT * DIN + 255) / 256, 256>>>(Wk, wkh, DOUT * DIN);
    convert_hi_kernel<<<(DOUT * DIN + 255) / 256, 256>>>(Wv, wvh, DOUT * DIN);

    // 2) projections (plain fp16): Q, K row-major; V transposed. grid = 1 wave.
    dim3 gproj(DOUT / 256, SEQ / 128);
    gemm_nt_kernel<OUT_HI>  <<<gproj, 512, GEMM_SMEM>>>(xh, wqh, nullptr, qh,  nullptr, DIN, DOUT, 1.0f);
    gemm_nt_kernel<OUT_HI>  <<<gproj, 512, GEMM_SMEM>>>(xh, wkh, nullptr, kh,  nullptr, DIN, DOUT, 1.0f);
    gemm_nt_kernel<OUT_HI_T><<<gproj, 512, GEMM_SMEM>>>(xh, wvh, nullptr, vth, nullptr, DIN, SEQ,  1.0f);

    // 3) scores + exp fused: P~ = exp(Q K^T / 32), fp16
    dim3 gsc(SEQ / 256, SEQ / 128);
    gemm_nt_kernel<OUT_EXP><<<gsc, 512, GEMM_SMEM>>>(qh, kh, nullptr, pph, nullptr, DIN, SEQ, 0.03125f);

    // 4) row inverse sums (deterministic reduction)
    rowinv_kernel<<<SEQ, 256>>>(pph, invrs);

    // 5) O = (P~ V) * invrs[m]   (P~ re-read halved vs 128-wide tiles)
    dim3 gout(DOUT / 256, SEQ / 128);
    gemm_nt_kernel<OUT_DIV><<<gout, 512, GEMM_SMEM>>>(pph, vth, out, nullptr, invrs, SEQ, DOUT, 1.0f);
}

// round 12
// speedup vs baseline: 3.0911x; 3.0911x over previous
#include <cuda_runtime.h>
#include <cuda_fp16.h>
#include <cstdint>
#include <cstddef>

using half_t = __half;

#define SEQ  8192
#define DIN  1024
#define DOUT 1024

// ---------------- device scratch (static: allowed) ----------------
__device__ half_t g_xh [SEQ * DIN];
__device__ half_t g_Wqh[DOUT * DIN];
__device__ half_t g_Wkh[DOUT * DIN];
__device__ half_t g_Wvh[DOUT * DIN];
__device__ half_t g_Qh [SEQ * DOUT];
__device__ half_t g_Kh [SEQ * DOUT];
__device__ half_t g_Vth[(size_t)DOUT * SEQ];   // V transposed [DOUT][SEQ]
__device__ half_t g_Ph [(size_t)SEQ * SEQ];    // unnormalized exp(scores), fp16
__device__ float  g_InvRS[SEQ];                // 1 / rowsum(exp)

// ---------------- helpers ----------------
__device__ __forceinline__ uint32_t smem_u32(const void* p) {
    uint32_t a;
    asm("{ .reg .u64 t; cvta.to.shared.u64 t, %1; cvt.u32.u64 %0, t; }" : "=r"(a) : "l"(p));
    return a;
}
__device__ __forceinline__ void cp16(uint32_t dst, const void* src) {
    asm volatile("cp.async.cg.shared.global [%0], [%1], 16;" :: "r"(dst), "l"(src));
}
#define CP_COMMIT() asm volatile("cp.async.commit_group;" ::: "memory")
#define CP_WAIT2()  asm volatile("cp.async.wait_group 2;" ::: "memory")

__device__ __forceinline__ void ldm4(uint32_t* r, uint32_t addr) {
    asm volatile("ldmatrix.sync.aligned.m8n8.x4.shared.b16 {%0,%1,%2,%3}, [%4];"
                 : "=r"(r[0]), "=r"(r[1]), "=r"(r[2]), "=r"(r[3]) : "r"(addr));
}
__device__ __forceinline__ void mma16816(float* d, const uint32_t* a, const uint32_t* b) {
    asm volatile(
        "mma.sync.aligned.m16n8k16.row.col.f32.f16.f16.f32 "
        "{%0,%1,%2,%3}, {%4,%5,%6,%7}, {%8,%9}, {%0,%1,%2,%3};"
        : "+f"(d[0]), "+f"(d[1]), "+f"(d[2]), "+f"(d[3])
        : "r"(a[0]), "r"(a[1]), "r"(a[2]), "r"(a[3]), "r"(b[0]), "r"(b[1]));
}

// ---------------- vectorized conversion: 8 elems/thread ----------------
__global__ void convert8_kernel(const float4* __restrict__ src, uint4* __restrict__ dst, int n8) {
    int i = blockIdx.x * blockDim.x + threadIdx.x;
    if (i < n8) {
        float4 a = src[2 * i];
        float4 b = src[2 * i + 1];
        __half2 h0 = __halves2half2(__float2half_rn(a.x), __float2half_rn(a.y));
        __half2 h1 = __halves2half2(__float2half_rn(a.z), __float2half_rn(a.w));
        __half2 h2 = __halves2half2(__float2half_rn(b.x), __float2half_rn(b.y));
        __half2 h3 = __halves2half2(__float2half_rn(b.z), __float2half_rn(b.w));
        uint4 o;
        o.x = *(uint32_t*)&h0;
        o.y = *(uint32_t*)&h1;
        o.z = *(uint32_t*)&h2;
        o.w = *(uint32_t*)&h3;
        dst[i] = o;
    }
}

// ---------------- GEMM: C[MxN] = alpha * A[MxK] * B[NxK]^T (plain fp16) ----------------
// 128x128 CTA tile, 256 threads, warp tile 64x32, 2 CTAs/SM, 4-stage cp.async.
#define OUT_HI    0
#define OUT_HI_T  1
#define OUT_EXP   2
#define OUT_DIV   3

#define KT      32              // K elements per stage
#define STRIDE  40              // smem row stride in halves (80 B, conflict-free)
#define TILE_H  (128 * STRIDE)  // 5120 halves per operand tile
#define TILE_B  (TILE_H * 2)    // 10240 bytes
#define STAGES  4
#define STAGE_B (2 * TILE_B)    // [A, B] tiles: 20480
#define GEMM_SMEM (STAGES * STAGE_B)  // 81920 -> 2 CTAs/SM (163840 < 228K)

template <int MODE>
__global__ __launch_bounds__(256, 2)
void gemm_nt_kernel(const half_t* __restrict__ Ah, const half_t* __restrict__ Bh,
                    float* __restrict__ outF, half_t* __restrict__ outH,
                    const float* __restrict__ invrs,
                    int K, int ldc, float alpha) {
    extern __shared__ half_t sm[];
    const uint32_t sbase = smem_u32(sm);
    const int tid  = threadIdx.x;
    const int lane = tid & 31;
    const int wid  = tid >> 5;
    const int m0 = blockIdx.y * 128;
    const int n0 = blockIdx.x * 128;
    const int wm = (wid & 1) * 64;         // warp M offset
    const int wn = (wid >> 1) * 32;        // warp N offset

    // --- cp.async addressing: thread t -> row t>>1, chunk pair (t&1)*2 ---
    const int lrow = tid >> 1;
    const int lj   = (tid & 1) * 2;
    const half_t* srcA = Ah + (size_t)(m0 + lrow) * K + lj * 8;
    const half_t* srcB = Bh + (size_t)(n0 + lrow) * K + lj * 8;
    const uint32_t doff = (uint32_t)((lrow * STRIDE + lj * 8) * 2);

    auto load_stage = [&](int s, int kt) {
        uint32_t dstb = sbase + s * STAGE_B + doff;
        const int ko = kt * KT;
        cp16(dstb + 0,           srcA + ko);
        cp16(dstb + 16,          srcA + ko + 8);
        cp16(dstb + TILE_B + 0,  srcB + ko);
        cp16(dstb + TILE_B + 16, srcB + ko + 8);
    };

    float acc[4][4][4];
#pragma unroll
    for (int mt = 0; mt < 4; mt++)
#pragma unroll
        for (int nt = 0; nt < 4; nt++)
#pragma unroll
            for (int e = 0; e < 4; e++) acc[mt][nt][e] = 0.0f;

    // ldmatrix address components
    const int arow    = wm + (lane & 15);
    const int acolsel = ((lane >> 4) & 1) * 8;
    const int brow    = wn + ((lane >> 4) & 1) * 8 + (lane & 7);
    const int bcolsel = ((lane >> 3) & 1) * 8;

    const int nkt = K / KT;
    // prologue: 3 stages in flight
    load_stage(0, 0); CP_COMMIT();
    load_stage(1, 1); CP_COMMIT();
    load_stage(2, 2); CP_COMMIT();

#pragma unroll 1
    for (int kt = 0; kt < nkt; kt++) {
        CP_WAIT2();
        __syncthreads();
        // write slot (kt+3)%4 == (kt-1)%4: computed last iter, reads done pre-barrier
        if (kt + 3 < nkt) load_stage((kt + 3) & 3, kt + 3);
        CP_COMMIT();

        const uint32_t stb = sbase + (kt & 3) * STAGE_B;
#pragma unroll
        for (int kk = 0; kk < 2; kk++) {
            const int kc = kk * 16;
            uint32_t a_h[4][4], b_h[4][2];
#pragma unroll
            for (int mt = 0; mt < 4; mt++) {
                uint32_t off = (uint32_t)(((arow + mt * 16) * STRIDE + kc + acolsel) * 2);
                ldm4(a_h[mt], stb + off);
            }
#pragma unroll
            for (int pt = 0; pt < 2; pt++) {
                uint32_t off = (uint32_t)(((brow + pt * 16) * STRIDE + kc + bcolsel) * 2);
                uint32_t r[4];
                ldm4(r, stb + TILE_B + off);
                b_h[2 * pt][0] = r[0]; b_h[2 * pt][1] = r[1];
                b_h[2 * pt + 1][0] = r[2]; b_h[2 * pt + 1][1] = r[3];
            }
#pragma unroll
            for (int mt = 0; mt < 4; mt++)
#pragma unroll
                for (int nt = 0; nt < 4; nt++)
                    mma16816(acc[mt][nt], a_h[mt], b_h[nt]);
        }
    }

    // ---------------- epilogue (register-direct) ----------------
    const int rr = lane >> 2;
    const int cc = (lane & 3) * 2;
#pragma unroll
    for (int mt = 0; mt < 4; mt++) {
        int gm = m0 + wm + mt * 16 + rr;
        float inv0 = 0.f, inv1 = 0.f;
        if (MODE == OUT_DIV) { inv0 = invrs[gm]; inv1 = invrs[gm + 8]; }
#pragma unroll
        for (int nt = 0; nt < 4; nt++) {
            int gn = n0 + wn + nt * 8 + cc;
#pragma unroll
            for (int h = 0; h < 2; h++) {
                float v0 = acc[mt][nt][2 * h + 0] * alpha;
                float v1 = acc[mt][nt][2 * h + 1] * alpha;
                int m = gm + h * 8;
                if (MODE == OUT_HI) {
                    *(__half2*)(outH + (size_t)m * ldc + gn) =
                        __halves2half2(__float2half_rn(v0), __float2half_rn(v1));
                } else if (MODE == OUT_HI_T) {
                    outH[(size_t)gn * ldc + m]       = __float2half_rn(v0);
                    outH[(size_t)(gn + 1) * ldc + m] = __float2half_rn(v1);
                } else if (MODE == OUT_EXP) {
                    float e0 = __expf(v0);
                    float e1 = __expf(v1);
                    *(__half2*)(outH + (size_t)m * ldc + gn) =
                        __halves2half2(__float2half_rn(e0), __float2half_rn(e1));
                } else {  // OUT_DIV
                    float inv = (h == 0) ? inv0 : inv1;
                    float2 v; v.x = v0 * inv; v.y = v1 * inv;
                    *(float2*)(outF + (size_t)m * ldc + gn) = v;
                }
            }
        }
    }
}

// ---------------- per-row inverse sum of P~ (deterministic, UNCHANGED from R9) ----------------
__global__ __launch_bounds__(256)
void rowinv_kernel(const half_t* __restrict__ Ph, float* __restrict__ inv) {
    __shared__ float red[8];
    const int row = blockIdx.x;
    const int tid = threadIdx.x;
    const __half2* p = (const __half2*)(Ph + (size_t)row * SEQ);

    float sum = 0.0f;
#pragma unroll 4
    for (int i = tid; i < SEQ / 2; i += 256) {
        float2 f = __half22float2(p[i]);
        sum += f.x + f.y;
    }
#pragma unroll
    for (int o = 16; o; o >>= 1) sum += __shfl_xor_sync(0xFFFFFFFFu, sum, o);
    if ((tid & 31) == 0) red[tid >> 5] = sum;
    __syncthreads();
    if (tid == 0) {
        float t = 0.0f;
#pragma unroll
        for (int j = 0; j < 8; j++) t += red[j];
        inv[row] = 1.0f / t;
    }
}

// ---------------- host ----------------
extern "C" void kernel_launch(void* const* d_in, const int* in_sizes, int n_in,
                              void* d_out, int out_size) {
    const float* x  = (const float*)d_in[0];
    const float* Wq = (const float*)d_in[1];
    const float* Wk = (const float*)d_in[2];
    const float* Wv = (const float*)d_in[3];
    float* out = (float*)d_out;

    half_t *xh, *wqh, *wkh, *wvh, *qh, *kh, *vth, *pph;
    float* invrs;
    cudaGetSymbolAddress((void**)&xh,    g_xh);
    cudaGetSymbolAddress((void**)&wqh,   g_Wqh);
    cudaGetSymbolAddress((void**)&wkh,   g_Wkh);
    cudaGetSymbolAddress((void**)&wvh,   g_Wvh);
    cudaGetSymbolAddress((void**)&qh,    g_Qh);
    cudaGetSymbolAddress((void**)&kh,    g_Kh);
    cudaGetSymbolAddress((void**)&vth,   g_Vth);
    cudaGetSymbolAddress((void**)&pph,   g_Ph);
    cudaGetSymbolAddress((void**)&invrs, g_InvRS);

    cudaFuncSetAttribute((const void*)gemm_nt_kernel<OUT_HI>,
                         cudaFuncAttributeMaxDynamicSharedMemorySize, GEMM_SMEM);
    cudaFuncSetAttribute((const void*)gemm_nt_kernel<OUT_HI_T>,
                         cudaFuncAttributeMaxDynamicSharedMemorySize, GEMM_SMEM);
    cudaFuncSetAttribute((const void*)gemm_nt_kernel<OUT_EXP>,
                         cudaFuncAttributeMaxDynamicSharedMemorySize, GEMM_SMEM);
    cudaFuncSetAttribute((const void*)gemm_nt_kernel<OUT_DIV>,
                         cudaFuncAttributeMaxDynamicSharedMemorySize, GEMM_SMEM);

    // 1) convert all fp32 inputs to fp16 (vectorized, elementwise rn — order-invariant)
    convert8_kernel<<<(SEQ * DIN / 8 + 255) / 256, 256>>>((const float4*)x,  (uint4*)xh,  SEQ * DIN / 8);
    convert8_kernel<<<(DOUT * DIN / 8 + 255) / 256, 256>>>((const float4*)Wq, (uint4*)wqh, DOUT * DIN / 8);
    convert8_kernel<<<(DOUT * DIN / 8 + 255) / 256, 256>>>((const float4*)Wk, (uint4*)wkh, DOUT * DIN / 8);
    convert8_kernel<<<(DOUT * DIN / 8 + 255) / 256, 256>>>((const float4*)Wv, (uint4*)wvh, DOUT * DIN / 8);

    // 2) projections (plain fp16): Q, K row-major; V transposed
    dim3 gproj(DOUT / 128, SEQ / 128);
    gemm_nt_kernel<OUT_HI>  <<<gproj, 256, GEMM_SMEM>>>(xh, wqh, nullptr, qh,  nullptr, DIN, DOUT, 1.0f);
    gemm_nt_kernel<OUT_HI>  <<<gproj, 256, GEMM_SMEM>>>(xh, wkh, nullptr, kh,  nullptr, DIN, DOUT, 1.0f);
    gemm_nt_kernel<OUT_HI_T><<<gproj, 256, GEMM_SMEM>>>(xh, wvh, nullptr, vth, nullptr, DIN, SEQ,  1.0f);

    // 3) scores + exp fused: P~ = exp(Q K^T / 32), fp16
    dim3 gsc(SEQ / 128, SEQ / 128);
    gemm_nt_kernel<OUT_EXP><<<gsc, 256, GEMM_SMEM>>>(qh, kh, nullptr, pph, nullptr, DIN, SEQ, 0.03125f);

    // 4) row inverse sums (deterministic reduction)
    rowinv_kernel<<<SEQ, 256>>>(pph, invrs);

    // 5) O = (P~ V) * invrs[m]
    dim3 gout(DOUT / 128, SEQ / 128);
    gemm_nt_kernel<OUT_DIV><<<gout, 256, GEMM_SMEM>>>(pph, vth, out, nullptr, invrs, SEQ, DOUT, 1.0f);
}

// round 13
// speedup vs baseline: 3.1776x; 1.0280x over previous
#include <cuda_runtime.h>
#include <cuda_fp16.h>
#include <cstdint>
#include <cstddef>

using half_t = __half;

#define SEQ  8192
#define DIN  1024
#define DOUT 1024

// ---------------- device scratch (static: allowed) ----------------
__device__ half_t g_xh [SEQ * DIN];
__device__ half_t g_Wqh[DOUT * DIN];
__device__ half_t g_Wkh[DOUT * DIN];
__device__ half_t g_Wvh[DOUT * DIN];
__device__ half_t g_Qh [SEQ * DOUT];
__device__ half_t g_Kh [SEQ * DOUT];
__device__ half_t g_Vth[(size_t)DOUT * SEQ];   // V transposed [DOUT][SEQ]
__device__ half_t g_Ph [(size_t)SEQ * SEQ];    // unnormalized exp(scores), fp16
__device__ float  g_InvRS[SEQ];                // 1 / rowsum(exp)

// ---------------- helpers ----------------
__device__ __forceinline__ uint32_t smem_u32(const void* p) {
    uint32_t a;
    asm("{ .reg .u64 t; cvta.to.shared.u64 t, %1; cvt.u32.u64 %0, t; }" : "=r"(a) : "l"(p));
    return a;
}
__device__ __forceinline__ void cp16(uint32_t dst, const void* src) {
    asm volatile("cp.async.cg.shared.global [%0], [%1], 16;" :: "r"(dst), "l"(src));
}
#define CP_COMMIT() asm volatile("cp.async.commit_group;" ::: "memory")
#define CP_WAIT2()  asm volatile("cp.async.wait_group 2;" ::: "memory")

__device__ __forceinline__ void ldm4(uint32_t* r, uint32_t addr) {
    asm volatile("ldmatrix.sync.aligned.m8n8.x4.shared.b16 {%0,%1,%2,%3}, [%4];"
                 : "=r"(r[0]), "=r"(r[1]), "=r"(r[2]), "=r"(r[3]) : "r"(addr));
}
__device__ __forceinline__ void mma16816(float* d, const uint32_t* a, const uint32_t* b) {
    asm volatile(
        "mma.sync.aligned.m16n8k16.row.col.f32.f16.f16.f32 "
        "{%0,%1,%2,%3}, {%4,%5,%6,%7}, {%8,%9}, {%0,%1,%2,%3};"
        : "+f"(d[0]), "+f"(d[1]), "+f"(d[2]), "+f"(d[3])
        : "r"(a[0]), "r"(a[1]), "r"(a[2]), "r"(a[3]), "r"(b[0]), "r"(b[1]));
}

// ---------------- single merged conversion kernel (elementwise, order-free) ----------------
#define XN8 (SEQ * DIN / 8)      // 1048576
#define WN8 (DOUT * DIN / 8)     // 131072
__global__ void convert_all_kernel(const float4* __restrict__ x,  const float4* __restrict__ wq,
                                   const float4* __restrict__ wk, const float4* __restrict__ wv,
                                   uint4* __restrict__ xh,  uint4* __restrict__ wqh,
                                   uint4* __restrict__ wkh, uint4* __restrict__ wvh) {
    int i = blockIdx.x * blockDim.x + threadIdx.x;
    const float4* src; uint4* dst; int j;
    if (i < XN8)                { src = x;  dst = xh;  j = i; }
    else if (i < XN8 + WN8)     { src = wq; dst = wqh; j = i - XN8; }
    else if (i < XN8 + 2 * WN8) { src = wk; dst = wkh; j = i - XN8 - WN8; }
    else if (i < XN8 + 3 * WN8) { src = wv; dst = wvh; j = i - XN8 - 2 * WN8; }
    else return;
    float4 a = src[2 * j];
    float4 b = src[2 * j + 1];
    __half2 h0 = __halves2half2(__float2half_rn(a.x), __float2half_rn(a.y));
    __half2 h1 = __halves2half2(__float2half_rn(a.z), __float2half_rn(a.w));
    __half2 h2 = __halves2half2(__float2half_rn(b.x), __float2half_rn(b.y));
    __half2 h3 = __halves2half2(__float2half_rn(b.z), __float2half_rn(b.w));
    uint4 o;
    o.x = *(uint32_t*)&h0;
    o.y = *(uint32_t*)&h1;
    o.z = *(uint32_t*)&h2;
    o.w = *(uint32_t*)&h3;
    dst[j] = o;
}

// ---------------- GEMM: C[MxN] = alpha * A[MxK] * B[NxK]^T (plain fp16) ----------------
// 128x128 CTA tile, 256 threads, warp tile 64x32, 2 CTAs/SM, 4-stage cp.async.
// OUT_PROJ: gridDim.z = 3 selects (Wq->Q), (Wk->K), (Wv->V^T) — one launch, 3 GEMMs.
#define OUT_PROJ  0
#define OUT_EXP   1
#define OUT_DIV   2

#define KT      32              // K elements per stage
#define STRIDE  40              // smem row stride in halves (80 B, conflict-free)
#define TILE_H  (128 * STRIDE)  // 5120 halves per operand tile
#define TILE_B  (TILE_H * 2)    // 10240 bytes
#define STAGES  4
#define STAGE_B (2 * TILE_B)    // [A, B] tiles: 20480
#define GEMM_SMEM (STAGES * STAGE_B)  // 81920 -> 2 CTAs/SM (163840 < 228K)

template <int MODE>
__global__ __launch_bounds__(256, 2)
void gemm_nt_kernel(const half_t* __restrict__ Ah, const half_t* __restrict__ Bh,
                    const half_t* __restrict__ Bh2, const half_t* __restrict__ Bh3,
                    float* __restrict__ outF, half_t* __restrict__ outH,
                    half_t* __restrict__ outH2, half_t* __restrict__ outH3,
                    const float* __restrict__ invrs,
                    int K, int ldc, float alpha) {
    extern __shared__ half_t sm[];
    const uint32_t sbase = smem_u32(sm);
    const int tid  = threadIdx.x;
    const int lane = tid & 31;
    const int wid  = tid >> 5;
    const int m0 = blockIdx.y * 128;
    const int n0 = blockIdx.x * 128;
    const int wm = (wid & 1) * 64;         // warp M offset
    const int wn = (wid >> 1) * 32;        // warp N offset

    const int which = (MODE == OUT_PROJ) ? blockIdx.z : 0;
    const half_t* Bsel = Bh;
    if (MODE == OUT_PROJ) Bsel = (which == 0) ? Bh : (which == 1) ? Bh2 : Bh3;

    // --- cp.async addressing: thread t -> row t>>1, chunk pair (t&1)*2 ---
    const int lrow = tid >> 1;
    const int lj   = (tid & 1) * 2;
    const half_t* srcA = Ah   + (size_t)(m0 + lrow) * K + lj * 8;
    const half_t* srcB = Bsel + (size_t)(n0 + lrow) * K + lj * 8;
    const uint32_t doff = (uint32_t)((lrow * STRIDE + lj * 8) * 2);

    auto load_stage = [&](int s, int kt) {
        uint32_t dstb = sbase + s * STAGE_B + doff;
        const int ko = kt * KT;
        cp16(dstb + 0,           srcA + ko);
        cp16(dstb + 16,          srcA + ko + 8);
        cp16(dstb + TILE_B + 0,  srcB + ko);
        cp16(dstb + TILE_B + 16, srcB + ko + 8);
    };

    float acc[4][4][4];
#pragma unroll
    for (int mt = 0; mt < 4; mt++)
#pragma unroll
        for (int nt = 0; nt < 4; nt++)
#pragma unroll
            for (int e = 0; e < 4; e++) acc[mt][nt][e] = 0.0f;

    // ldmatrix address components
    const int arow    = wm + (lane & 15);
    const int acolsel = ((lane >> 4) & 1) * 8;
    const int brow    = wn + ((lane >> 4) & 1) * 8 + (lane & 7);
    const int bcolsel = ((lane >> 3) & 1) * 8;

    const int nkt = K / KT;
    // prologue: 3 stages in flight
    load_stage(0, 0); CP_COMMIT();
    load_stage(1, 1); CP_COMMIT();
    load_stage(2, 2); CP_COMMIT();

#pragma unroll 1
    for (int kt = 0; kt < nkt; kt++) {
        CP_WAIT2();
        __syncthreads();
        // write slot (kt+3)%4 == (kt-1)%4: computed last iter, reads done pre-barrier
        if (kt + 3 < nkt) load_stage((kt + 3) & 3, kt + 3);
        CP_COMMIT();

        const uint32_t stb = sbase + (kt & 3) * STAGE_B;
#pragma unroll
        for (int kk = 0; kk < 2; kk++) {
            const int kc = kk * 16;
            uint32_t a_h[4][4], b_h[4][2];
#pragma unroll
            for (int mt = 0; mt < 4; mt++) {
                uint32_t off = (uint32_t)(((arow + mt * 16) * STRIDE + kc + acolsel) * 2);
                ldm4(a_h[mt], stb + off);
            }
#pragma unroll
            for (int pt = 0; pt < 2; pt++) {
                uint32_t off = (uint32_t)(((brow + pt * 16) * STRIDE + kc + bcolsel) * 2);
                uint32_t r[4];
                ldm4(r, stb + TILE_B + off);
                b_h[2 * pt][0] = r[0]; b_h[2 * pt][1] = r[1];
                b_h[2 * pt + 1][0] = r[2]; b_h[2 * pt + 1][1] = r[3];
            }
#pragma unroll
            for (int mt = 0; mt < 4; mt++)
#pragma unroll
                for (int nt = 0; nt < 4; nt++)
                    mma16816(acc[mt][nt], a_h[mt], b_h[nt]);
        }
    }

    // ---------------- epilogue (register-direct) ----------------
    const int rr = lane >> 2;
    const int cc = (lane & 3) * 2;
#pragma unroll
    for (int mt = 0; mt < 4; mt++) {
        int gm = m0 + wm + mt * 16 + rr;
        float inv0 = 0.f, inv1 = 0.f;
        if (MODE == OUT_DIV) { inv0 = invrs[gm]; inv1 = invrs[gm + 8]; }
#pragma unroll
        for (int nt = 0; nt < 4; nt++) {
            int gn = n0 + wn + nt * 8 + cc;
#pragma unroll
            for (int h = 0; h < 2; h++) {
                float v0 = acc[mt][nt][2 * h + 0] * alpha;
                float v1 = acc[mt][nt][2 * h + 1] * alpha;
                int m = gm + h * 8;
                if (MODE == OUT_PROJ) {
                    if (which == 0) {
                        *(__half2*)(outH + (size_t)m * DOUT + gn) =
                            __halves2half2(__float2half_rn(v0), __float2half_rn(v1));
                    } else if (which == 1) {
                        *(__half2*)(outH2 + (size_t)m * DOUT + gn) =
                            __halves2half2(__float2half_rn(v0), __float2half_rn(v1));
                    } else {   // V: transposed store, ldc = SEQ
                        outH3[(size_t)gn * SEQ + m]       = __float2half_rn(v0);
                        outH3[(size_t)(gn + 1) * SEQ + m] = __float2half_rn(v1);
                    }
                } else if (MODE == OUT_EXP) {
                    float e0 = __expf(v0);
                    float e1 = __expf(v1);
                    *(__half2*)(outH + (size_t)m * ldc + gn) =
                        __halves2half2(__float2half_rn(e0), __float2half_rn(e1));
                } else {  // OUT_DIV
                    float inv = (h == 0) ? inv0 : inv1;
                    float2 v; v.x = v0 * inv; v.y = v1 * inv;
                    *(float2*)(outF + (size_t)m * ldc + gn) = v;
                }
            }
        }
    }
}

// ---------------- per-row inverse sum of P~ (deterministic, UNCHANGED) ----------------
__global__ __launch_bounds__(256)
void rowinv_kernel(const half_t* __restrict__ Ph, float* __restrict__ inv) {
    __shared__ float red[8];
    const int row = blockIdx.x;
    const int tid = threadIdx.x;
    const __half2* p = (const __half2*)(Ph + (size_t)row * SEQ);

    float sum = 0.0f;
#pragma unroll 4
    for (int i = tid; i < SEQ / 2; i += 256) {
        float2 f = __half22float2(p[i]);
        sum += f.x + f.y;
    }
#pragma unroll
    for (int o = 16; o; o >>= 1) sum += __shfl_xor_sync(0xFFFFFFFFu, sum, o);
    if ((tid & 31) == 0) red[tid >> 5] = sum;
    __syncthreads();
    if (tid == 0) {
        float t = 0.0f;
#pragma unroll
        for (int j = 0; j < 8; j++) t += red[j];
        inv[row] = 1.0f / t;
    }
}

// ---------------- host ----------------
extern "C" void kernel_launch(void* const* d_in, const int* in_sizes, int n_in,
                              void* d_out, int out_size) {
    const float* x  = (const float*)d_in[0];
    const float* Wq = (const float*)d_in[1];
    const float* Wk = (const float*)d_in[2];
    const float* Wv = (const float*)d_in[3];
    float* out = (float*)d_out;

    half_t *xh, *wqh, *wkh, *wvh, *qh, *kh, *vth, *pph;
    float* invrs;
    cudaGetSymbolAddress((void**)&xh,    g_xh);
    cudaGetSymbolAddress((void**)&wqh,   g_Wqh);
    cudaGetSymbolAddress((void**)&wkh,   g_Wkh);
    cudaGetSymbolAddress((void**)&wvh,   g_Wvh);
    cudaGetSymbolAddress((void**)&qh,    g_Qh);
    cudaGetSymbolAddress((void**)&kh,    g_Kh);
    cudaGetSymbolAddress((void**)&vth,   g_Vth);
    cudaGetSymbolAddress((void**)&pph,   g_Ph);
    cudaGetSymbolAddress((void**)&invrs, g_InvRS);

    cudaFuncSetAttribute((const void*)gemm_nt_kernel<OUT_PROJ>,
                         cudaFuncAttributeMaxDynamicSharedMemorySize, GEMM_SMEM);
    cudaFuncSetAttribute((const void*)gemm_nt_kernel<OUT_EXP>,
                         cudaFuncAttributeMaxDynamicSharedMemorySize, GEMM_SMEM);
    cudaFuncSetAttribute((const void*)gemm_nt_kernel<OUT_DIV>,
                         cudaFuncAttributeMaxDynamicSharedMemorySize, GEMM_SMEM);

    // 1) convert all fp32 inputs to fp16 in ONE launch (elementwise rn)
    {
        int total8 = XN8 + 3 * WN8;
        convert_all_kernel<<<(total8 + 255) / 256, 256>>>(
            (const float4*)x, (const float4*)Wq, (const float4*)Wk, (const float4*)Wv,
            (uint4*)xh, (uint4*)wqh, (uint4*)wkh, (uint4*)wvh);
    }

    // 2) ALL projections in ONE launch: z=0 Q, z=1 K, z=2 V^T (1536 CTAs, small tail)
    dim3 gproj(DOUT / 128, SEQ / 128, 3);
    gemm_nt_kernel<OUT_PROJ><<<gproj, 256, GEMM_SMEM>>>(
        xh, wqh, wkh, wvh, nullptr, qh, kh, vth, nullptr, DIN, DOUT, 1.0f);

    // 3) scores + exp fused: P~ = exp(Q K^T / 32), fp16
    dim3 gsc(SEQ / 128, SEQ / 128);
    gemm_nt_kernel<OUT_EXP><<<gsc, 256, GEMM_SMEM>>>(
        qh, kh, nullptr, nullptr, nullptr, pph, nullptr, nullptr, nullptr, DIN, SEQ, 0.03125f);

    // 4) row inverse sums (deterministic reduction)
    rowinv_kernel<<<SEQ, 256>>>(pph, invrs);

    // 5) O = (P~ V) * invrs[m]
    dim3 gout(DOUT / 128, SEQ / 128);
    gemm_nt_kernel<OUT_DIV><<<gout, 256, GEMM_SMEM>>>(
        pph, vth, nullptr, nullptr, out, nullptr, nullptr, nullptr, invrs, SEQ, DOUT, 1.0f);
}